// round 2
// baseline (speedup 1.0000x reference)
#include <cuda_runtime.h>
#include <math.h>

// Problem constants (fixed shapes from reference)
#define BB 8
#define CC 512
#define LL 8192
#define KS 3
#define WELEMS (CC*CC*KS)   // 786432

// Conv tiling
#define O_TILE 64
#define L_TILE 256
#define CI 8
#define HALO 5                      // max dilation
#define LXS (L_TILE + 2*HALO)       // 266
#define NCHUNK (CC/CI)              // 64
#define XELEMS (CI*LXS)             // 2128
#define XSTAGE ((XELEMS + 255)/256) // 9
#define WSTAGE ((CI*KS*O_TILE)/256) // 6

// Scratch (no cudaMalloc allowed)
__device__ float g_h[(size_t)BB*CC*LL];       // intermediate h per branch
__device__ float g_wq[6][CC*KS*CC];           // quantized weights, layout [i][k][o]
__device__ float g_partial[256];
__device__ float g_scale;

// ---- packed fp32x2 helpers (B300: FFMA rt=2/SMSP, packed path needed for 128 FMA/cyc/SM) ----
__device__ __forceinline__ unsigned long long pk2(float lo, float hi) {
    unsigned long long r;
    asm("mov.b64 %0, {%1, %2};" : "=l"(r) : "f"(lo), "f"(hi));
    return r;
}
__device__ __forceinline__ void upk2(unsigned long long v, float& lo, float& hi) {
    asm("mov.b64 {%0, %1}, %2;" : "=f"(lo), "=f"(hi) : "l"(v));
}
__device__ __forceinline__ void ffma2(unsigned long long& d, unsigned long long a, unsigned long long b) {
    asm("fma.rn.f32x2 %0, %1, %2, %0;" : "+l"(d) : "l"(a), "l"(b));
}

// ---- weight quantization: scale = mean(|w|) + 1e-5; wq = clip(round(w/scale),-1,1)*scale ----
__global__ void absmean_partial_k(const float* __restrict__ w) {
    __shared__ float red[256];
    float s = 0.f;
    for (int i = blockIdx.x*256 + threadIdx.x; i < WELEMS; i += 256*256)
        s += fabsf(w[i]);
    red[threadIdx.x] = s;
    __syncthreads();
    for (int st = 128; st > 0; st >>= 1) {
        if (threadIdx.x < st) red[threadIdx.x] += red[threadIdx.x + st];
        __syncthreads();
    }
    if (threadIdx.x == 0) g_partial[blockIdx.x] = red[0];
}

__global__ void absmean_final_k() {
    __shared__ float red[256];
    red[threadIdx.x] = g_partial[threadIdx.x];
    __syncthreads();
    for (int st = 128; st > 0; st >>= 1) {
        if (threadIdx.x < st) red[threadIdx.x] += red[threadIdx.x + st];
        __syncthreads();
    }
    if (threadIdx.x == 0) g_scale = red[0] / (float)WELEMS + 1e-5f;
}

// w layout [o][i][k] -> wq layout [i][k][o] (contiguous output channels)
__global__ void quantize_k(const float* __restrict__ w, float* __restrict__ wq) {
    int idx = blockIdx.x*blockDim.x + threadIdx.x;
    if (idx >= WELEMS) return;
    float s = g_scale;
    int k = idx % KS;
    int i = (idx / KS) % CC;
    int o = idx / (KS*CC);
    float q = rintf(w[idx] / s);           // round-half-even == jnp.round
    q = fminf(1.f, fmaxf(-1.f, q));
    wq[(i*KS + k)*CC + o] = q * s;
}

// ---- fused conv kernel ----
// mode 0: dst = leakyrelu(conv(src) + bias)
// mode 1: dst += conv(src) + bias       (residual accumulate, dst is running x)
__global__ void __launch_bounds__(256, 2)
conv_kernel(const float* __restrict__ src, float* __restrict__ dst,
            const float* __restrict__ bias, const float* __restrict__ Wq,
            int dil, int mode)
{
    __shared__ __align__(16) float Xs[2][CI][LXS];
    __shared__ __align__(16) float Ws[2][CI][KS][O_TILE];

    const int tid = threadIdx.x;
    const int lt  = tid & 31;     // 32 l-lanes
    const int ot  = tid >> 5;     // 8 o-groups of 8
    const int l0  = blockIdx.x * L_TILE;
    const int o0  = blockIdx.y * O_TILE;
    const int b   = blockIdx.z;

    const float* xb = src + (size_t)b * CC * LL;

    // Staging metadata (chunk-invariant)
    int  xoff[XSTAGE]; bool xval[XSTAGE]; int xsid[XSTAGE];
#pragma unroll
    for (int s = 0; s < XSTAGE; s++) {
        int t   = tid + s*256;
        int row = t / LXS;
        int col = t - row*LXS;
        int gl  = l0 - HALO + col;
        xval[s] = (t < XELEMS) && (gl >= 0) && (gl < LL);
        xoff[s] = row*LL + gl;
        xsid[s] = t;
    }
    int woff[WSTAGE];
#pragma unroll
    for (int s = 0; s < WSTAGE; s++) {
        int t   = tid + s*256;
        int r   = t / (KS*O_TILE);
        int rem = t - r*(KS*O_TILE);
        int k   = rem >> 6;
        int o   = rem & 63;
        woff[s] = (r*KS + k)*CC + o0 + o;
    }

    // Prologue: load + store chunk 0
    float xr[XSTAGE], wr[WSTAGE];
#pragma unroll
    for (int s = 0; s < XSTAGE; s++) xr[s] = xval[s] ? __ldg(&xb[xoff[s]]) : 0.f;
#pragma unroll
    for (int s = 0; s < WSTAGE; s++) wr[s] = __ldg(&Wq[woff[s]]);
    {
        float* xs0 = &Xs[0][0][0];
        float* ws0 = &Ws[0][0][0][0];
#pragma unroll
        for (int s = 0; s < XSTAGE; s++) if (xsid[s] < XELEMS) xs0[xsid[s]] = xr[s];
#pragma unroll
        for (int s = 0; s < WSTAGE; s++) ws0[tid + s*256] = wr[s];
    }
    __syncthreads();

    unsigned long long acc[4][8];   // [o-pair][l] ; each packs 2 adjacent o
#pragma unroll
    for (int p = 0; p < 4; p++)
#pragma unroll
        for (int j = 0; j < 8; j++) acc[p][j] = 0ull;

    const int offk0 = HALO - dil, offk1 = HALO, offk2 = HALO + dil;

    int cur = 0;
    for (int c = 0; c < NCHUNK; c++) {
        // Prefetch next chunk gmem->regs (overlaps with compute below)
        if (c + 1 < NCHUNK) {
            int xbase = (c+1)*CI*LL;
#pragma unroll
            for (int s = 0; s < XSTAGE; s++) xr[s] = xval[s] ? __ldg(&xb[xbase + xoff[s]]) : 0.f;
            int wbase = (c+1)*CI*KS*CC;
#pragma unroll
            for (int s = 0; s < WSTAGE; s++) wr[s] = __ldg(&Wq[wbase + woff[s]]);
        }

        // Compute current chunk
#pragma unroll
        for (int ci = 0; ci < CI; ci++) {
            const float* xrow = &Xs[cur][ci][lt];
#pragma unroll
            for (int k = 0; k < KS; k++) {
                const float4* wp4 = (const float4*)&Ws[cur][ci][k][ot*8];
                float4 wa = wp4[0];
                float4 wb = wp4[1];
                unsigned long long w0 = pk2(wa.x, wa.y);
                unsigned long long w1 = pk2(wa.z, wa.w);
                unsigned long long w2 = pk2(wb.x, wb.y);
                unsigned long long w3 = pk2(wb.z, wb.w);
                const float* xk = xrow + (k == 0 ? offk0 : (k == 1 ? offk1 : offk2));
#pragma unroll
                for (int j = 0; j < 8; j++) {
                    float xv = xk[32*j];
                    unsigned long long xd = pk2(xv, xv);
                    ffma2(acc[0][j], w0, xd);
                    ffma2(acc[1][j], w1, xd);
                    ffma2(acc[2][j], w2, xd);
                    ffma2(acc[3][j], w3, xd);
                }
            }
        }
        __syncthreads();
        if (c + 1 < NCHUNK) {
            float* xsn = &Xs[cur^1][0][0];
            float* wsn = &Ws[cur^1][0][0][0];
#pragma unroll
            for (int s = 0; s < XSTAGE; s++) if (xsid[s] < XELEMS) xsn[xsid[s]] = xr[s];
#pragma unroll
            for (int s = 0; s < WSTAGE; s++) wsn[tid + s*256] = wr[s];
        }
        __syncthreads();
        cur ^= 1;
    }

    // Epilogue
#pragma unroll
    for (int p = 0; p < 4; p++) {
        int o = o0 + ot*8 + 2*p;
        float b0v = bias[o];
        float b1v = bias[o+1];
        float* d0 = dst + ((size_t)b*CC + o)*LL + l0 + lt;
        float* d1 = d0 + LL;
#pragma unroll
        for (int j = 0; j < 8; j++) {
            float v0, v1;
            upk2(acc[p][j], v0, v1);
            v0 += b0v; v1 += b1v;
            if (mode == 0) {
                v0 = (v0 >= 0.f) ? v0 : 0.1f*v0;
                v1 = (v1 >= 0.f) ? v1 : 0.1f*v1;
                d0[32*j] = v0;
                d1[32*j] = v1;
            } else {
                d0[32*j] += v0;
                d1[32*j] += v1;
            }
        }
    }
}

extern "C" void kernel_launch(void* const* d_in, const int* in_sizes, int n_in,
                              void* d_out, int out_size) {
    const float* x = (const float*)d_in[0];
    float* out = (float*)d_out;

    void* hp;  cudaGetSymbolAddress(&hp,  g_h);
    void* wqp; cudaGetSymbolAddress(&wqp, g_wq);
    float* h      = (float*)hp;
    float* wqbase = (float*)wqp;

    // Seed running x into d_out
    cudaMemcpyAsync(out, x, sizeof(float)*(size_t)BB*CC*LL, cudaMemcpyDeviceToDevice, 0);

    // Quantize all 6 weight tensors (w at d_in indices 1,3,5,7,9,11)
    for (int t = 0; t < 6; t++) {
        const float* w = (const float*)d_in[1 + 2*t];
        absmean_partial_k<<<256, 256>>>(w);
        absmean_final_k<<<1, 256>>>();
        quantize_k<<<(WELEMS + 255)/256, 256>>>(w, wqbase + (size_t)t*CC*KS*CC);
    }

    dim3 grid(LL/L_TILE, CC/O_TILE, BB);   // 32 x 8 x 8
    const int dils[3] = {1, 3, 5};
    for (int br = 0; br < 3; br++) {
        const float* bA = (const float*)d_in[2 + 4*br];
        const float* bB = (const float*)d_in[4 + 4*br];
        // h = leakyrelu(convA_dilated(x))
        conv_kernel<<<grid, 256>>>(out, h, bA, wqbase + (size_t)(2*br  )*CC*KS*CC, dils[br], 0);
        // x += convB_dense(h)
        conv_kernel<<<grid, 256>>>(h, out, bB, wqbase + (size_t)(2*br+1)*CC*KS*CC, 1, 1);
    }
}

// round 4
// speedup vs baseline: 3.2099x; 3.2099x over previous
#include <cuda_runtime.h>
#include <cuda_bf16.h>
#include <math.h>
#include <stdint.h>

// ---------------- problem constants ----------------
#define BB 8
#define CC 512
#define LL 8192
#define KS 3
#define WELEMS (CC*CC*KS)

// ---------------- layout / tiling ----------------
#define XL 8448                 // padded rows per batch: 8 front pad + 8192 + tail pad (zeros)
#define XPAD 8
#define OT 64                   // block O tile
#define LT 128                  // block L tile
#define KC 32                   // ci per chunk
#define NCHUNK (CC/KC)          // 16
#define XROWS 138               // LT + 2*5 halo
#define PITCH 80                // smem row pitch bytes (64B data) -> conflict-free ldmatrix
#define W_OFF 0
#define W_BYTES (3*OT*PITCH)    // 15360
#define X_OFF W_BYTES
#define X_BYTES (2*XROWS*PITCH) // 22080
#define STAGE_BYTES 37504       // aligned(W_BYTES + X_BYTES, 128)
#define NSEG_W (3*OT*4)         // 768 16B segments
#define NSEG_X (2*XROWS*4)      // 1104
#define NSEG (NSEG_W + NSEG_X)  // 1872
#define SMEM_TOTAL (2*STAGE_BYTES)  // 75008 (epilogue yt reuses stage0)
#define YPITCH 133              // fp32 epilogue pitch (133%32=5 -> conflict-free columns)

// ---------------- device scratch (zero-initialized; pads stay zero) ----------------
__device__ __align__(1024) __nv_bfloat16 g_xt_hi[(size_t)BB*XL*CC];
__device__ __align__(1024) __nv_bfloat16 g_xt_lo[(size_t)BB*XL*CC];
__device__ __align__(1024) __nv_bfloat16 g_ht_hi[(size_t)BB*XL*CC];
__device__ __align__(1024) __nv_bfloat16 g_ht_lo[(size_t)BB*XL*CC];
__device__ __align__(1024) __nv_bfloat16 g_q[(size_t)18*CC*CC];   // [widx*3+tap][o][ci]
__device__ float g_partial[256];
__device__ float g_scales[6];

// ---------------- asm helpers ----------------
__device__ __forceinline__ uint32_t smem_u32(const void* p) {
    uint32_t a;
    asm("{ .reg .u64 t; cvta.to.shared.u64 t, %1; cvt.u32.u64 %0, t; }" : "=r"(a) : "l"(p));
    return a;
}
__device__ __forceinline__ void cp16(uint32_t saddr, const void* gaddr) {
    asm volatile("cp.async.cg.shared.global [%0], [%1], 16;" :: "r"(saddr), "l"(gaddr));
}
__device__ __forceinline__ void cp_commit() { asm volatile("cp.async.commit_group;"); }
template<int N> __device__ __forceinline__ void cp_wait() {
    asm volatile("cp.async.wait_group %0;" :: "n"(N));
}
__device__ __forceinline__ void ldm_x4(uint32_t* r, uint32_t addr) {
    asm volatile("ldmatrix.sync.aligned.m8n8.x4.shared.b16 {%0,%1,%2,%3}, [%4];"
                 : "=r"(r[0]), "=r"(r[1]), "=r"(r[2]), "=r"(r[3]) : "r"(addr));
}
__device__ __forceinline__ void ldm_x2(uint32_t* r, uint32_t addr) {
    asm volatile("ldmatrix.sync.aligned.m8n8.x2.shared.b16 {%0,%1}, [%2];"
                 : "=r"(r[0]), "=r"(r[1]) : "r"(addr));
}
__device__ __forceinline__ void mma16816(float* d, const uint32_t* a, const uint32_t* b) {
    asm volatile("mma.sync.aligned.m16n8k16.row.col.f32.bf16.bf16.f32 "
                 "{%0,%1,%2,%3}, {%4,%5,%6,%7}, {%8,%9}, {%0,%1,%2,%3};"
                 : "+f"(d[0]), "+f"(d[1]), "+f"(d[2]), "+f"(d[3])
                 : "r"(a[0]), "r"(a[1]), "r"(a[2]), "r"(a[3]), "r"(b[0]), "r"(b[1]));
}

// ---------------- weight quantization ----------------
__global__ void absmean_partial_k(const float* __restrict__ w) {
    __shared__ float red[256];
    float s = 0.f;
    for (int i = blockIdx.x*256 + threadIdx.x; i < WELEMS; i += 256*256) s += fabsf(w[i]);
    red[threadIdx.x] = s;
    __syncthreads();
    for (int st = 128; st > 0; st >>= 1) {
        if (threadIdx.x < st) red[threadIdx.x] += red[threadIdx.x + st];
        __syncthreads();
    }
    if (threadIdx.x == 0) g_partial[blockIdx.x] = red[0];
}
__global__ void absmean_final_k(int widx) {
    __shared__ float red[256];
    red[threadIdx.x] = g_partial[threadIdx.x];
    __syncthreads();
    for (int st = 128; st > 0; st >>= 1) {
        if (threadIdx.x < st) red[threadIdx.x] += red[threadIdx.x + st];
        __syncthreads();
    }
    if (threadIdx.x == 0) g_scales[widx] = red[0] / (float)WELEMS + 1e-5f;
}
// src w [o][i][k] -> g_q[(widx*3+k)][o][i] ternary bf16 (exact; scale applied in epilogue)
__global__ void quantize_k(const float* __restrict__ w, int widx) {
    int idx = blockIdx.x*256 + threadIdx.x;
    if (idx >= WELEMS) return;
    float s = g_scales[widx];
    int k = idx % KS;
    int i = (idx / KS) % CC;
    int o = idx / (KS*CC);
    float q = rintf(w[idx] / s);
    q = fminf(1.f, fmaxf(-1.f, q));
    g_q[(((size_t)widx*3 + k)*CC + o)*CC + i] = __float2bfloat16_rn(q);
}

// ---------------- initial split+transpose: fp32 [b][c][l] -> bf16 hi/lo [b][l][c] ----------------
__global__ void transpose_split_k(const float* __restrict__ src) {
    __shared__ float t[32][65];
    int b = blockIdx.z, c0 = blockIdx.y*32, l0 = blockIdx.x*64;
#pragma unroll
    for (int k = 0; k < 8; k++) {
        int idx = threadIdx.x + k*256;
        int cl = idx >> 6, ll_ = idx & 63;
        t[cl][ll_] = src[((size_t)b*CC + c0 + cl)*LL + l0 + ll_];
    }
    __syncthreads();
#pragma unroll
    for (int k = 0; k < 8; k++) {
        int idx = threadIdx.x + k*256;
        int ll_ = idx >> 5, cl = idx & 31;
        float v = t[cl][ll_];
        __nv_bfloat16 hi = __float2bfloat16_rn(v);
        __nv_bfloat16 lo = __float2bfloat16_rn(v - __bfloat162float(hi));
        size_t off = ((size_t)b*XL + XPAD + l0 + ll_)*CC + c0 + cl;
        g_xt_hi[off] = hi;
        g_xt_lo[off] = lo;
    }
}

// ---------------- fused conv kernel (mma.sync implicit GEMM) ----------------
// D[o=64][l=128] = sum over ci(512), taps(3), halves(2) of Q_tap[o][ci] * Xhalf[l+(tap-1)d][ci]
// mode 0: out = leakyrelu(s*D + bias) -> bf16 hi/lo [b][l][c]
// mode 1: xio += s*D + bias (fp32 [b][c][l]); new x -> bf16 hi/lo [b][l][c]
__global__ void __launch_bounds__(256, 2)
conv_mma_kernel(const __nv_bfloat16* __restrict__ Wq,   // [3][512][512] for this layer
                const __nv_bfloat16* __restrict__ bhi,  // [b][XL][512]
                const __nv_bfloat16* __restrict__ blo,
                const float* __restrict__ bias,
                float* __restrict__ xio,
                __nv_bfloat16* __restrict__ out_hi,
                __nv_bfloat16* __restrict__ out_lo,
                int widx, int dil, int mode)
{
    extern __shared__ char smem[];
    const uint32_t sbase = smem_u32(smem);

    const int tid  = threadIdx.x;
    const int lane = tid & 31;
    const int w    = tid >> 5;
    const int o_w  = (w >> 2) * 32;     // warp O offset (0/32)
    const int l_w  = (w & 3) * 32;      // warp L offset (0..96)
    const int o0   = blockIdx.x * OT;
    const int l0   = blockIdx.y * LT;
    const int b    = blockIdx.z;

    // ---- per-thread cp.async segment table (chunk-invariant; +64B per chunk) ----
    uint32_t soff[8]; const char* gp[8]; int nseg = 0;
#pragma unroll
    for (int i = 0; i < 8; i++) {
        int s = tid + i*256;
        if (s < NSEG) {
            nseg = i + 1;
            if (s < NSEG_W) {
                int tap = s >> 8, rr = (s & 255) >> 2, sg = s & 3;
                soff[i] = W_OFF + (uint32_t)(tap*OT + rr)*PITCH + sg*16;
                gp[i] = (const char*)(Wq + ((size_t)tap*CC + o0 + rr)*CC) + sg*16;
            } else {
                int t2 = s - NSEG_W;
                int half = t2 / (XROWS*4), rr = (t2 % (XROWS*4)) >> 2, sg = t2 & 3;
                soff[i] = X_OFF + (uint32_t)(half*XROWS + rr)*PITCH + sg*16;
                const __nv_bfloat16* base = half ? blo : bhi;
                gp[i] = (const char*)(base + ((size_t)b*XL + XPAD + l0 - 5 + rr)*CC) + sg*16;
            }
        }
    }

    // ---- ldmatrix base addresses ----
    // A (W, row-major [o][ci]): x4 mats: (r0-7,k0),(r8-15,k0),(r0-7,k+16B),(r8-15,k+16B)
    uint32_t a_base[2];
#pragma unroll
    for (int m = 0; m < 2; m++)
        a_base[m] = sbase + W_OFF
                  + (uint32_t)(o_w + m*16 + (lane & 7) + ((lane >> 3) & 1)*8)*PITCH
                  + (lane >> 4)*16;
    // B (X, [l][ci] k-contig): x2 mats: (n0-7,k0),(n0-7,k+16B); lanes 0-15 drive addresses
    uint32_t b_base[4];
#pragma unroll
    for (int n = 0; n < 4; n++)
        b_base[n] = sbase + X_OFF
                  + (uint32_t)(l_w + n*8 + (lane & 7))*PITCH
                  + ((lane >> 3) & 1)*16;

    float acc[2][4][4];
#pragma unroll
    for (int m = 0; m < 2; m++)
#pragma unroll
        for (int n = 0; n < 4; n++)
#pragma unroll
            for (int e = 0; e < 4; e++) acc[m][n][e] = 0.f;

    const int S0 = 5 - dil, S1 = 5, S2 = 5 + dil;
    const int Sx[3] = {S0, S1, S2};

    // ---- prologue: issue chunks 0 and 1 ----
#pragma unroll
    for (int i = 0; i < 8; i++) if (i < nseg) cp16(sbase + soff[i], gp[i]);
    cp_commit();
#pragma unroll
    for (int i = 0; i < 8; i++) if (i < nseg) cp16(sbase + STAGE_BYTES + soff[i], gp[i] + 64);
    cp_commit();

    for (int c = 0; c < NCHUNK; c++) {
        if (c < NCHUNK - 2) cp_wait<1>(); else cp_wait<0>();
        __syncthreads();
        const uint32_t stg = (uint32_t)(c & 1) * STAGE_BYTES;
#pragma unroll
        for (int k16 = 0; k16 < 2; k16++) {
#pragma unroll
            for (int tap = 0; tap < 3; tap++) {
                uint32_t afrag[2][4];
#pragma unroll
                for (int m = 0; m < 2; m++)
                    ldm_x4(afrag[m], a_base[m] + stg + (uint32_t)tap*(OT*PITCH) + k16*32);
#pragma unroll
                for (int half = 0; half < 2; half++) {
                    uint32_t bfrag[4][2];
                    const uint32_t boff = stg + (uint32_t)(half*XROWS + Sx[tap])*PITCH + k16*32;
#pragma unroll
                    for (int n = 0; n < 4; n++) ldm_x2(bfrag[n], b_base[n] + boff);
#pragma unroll
                    for (int m = 0; m < 2; m++)
#pragma unroll
                        for (int n = 0; n < 4; n++)
                            mma16816(acc[m][n], afrag[m], bfrag[n]);
                }
            }
        }
        __syncthreads();
        if (c + 2 < NCHUNK) {
            const int adv = (c + 2) * 64;
#pragma unroll
            for (int i = 0; i < 8; i++)
                if (i < nseg) cp16(sbase + stg + soff[i], gp[i] + adv);
            cp_commit();
        }
    }

    // ---- epilogue: stage y = s*acc + bias (leaky if mode 0) into smem [o][l] ----
    float* yt = (float*)smem;                 // reuses pipeline smem; pitch YPITCH
    const float s = g_scales[widx];
    const int g  = lane >> 2;
    const int tg = lane & 3;
#pragma unroll
    for (int m = 0; m < 2; m++) {
        const int r0 = o_w + m*16 + g;
        const float bv0 = bias[o0 + r0];
        const float bv8 = bias[o0 + r0 + 8];
#pragma unroll
        for (int n = 0; n < 4; n++) {
            const int col = l_w + n*8 + tg*2;
            float y0 = fmaf(s, acc[m][n][0], bv0);
            float y1 = fmaf(s, acc[m][n][1], bv0);
            float y2 = fmaf(s, acc[m][n][2], bv8);
            float y3 = fmaf(s, acc[m][n][3], bv8);
            if (mode == 0) {
                y0 = (y0 >= 0.f) ? y0 : 0.1f*y0;
                y1 = (y1 >= 0.f) ? y1 : 0.1f*y1;
                y2 = (y2 >= 0.f) ? y2 : 0.1f*y2;
                y3 = (y3 >= 0.f) ? y3 : 0.1f*y3;
            }
            yt[r0*YPITCH + col]       = y0;
            yt[r0*YPITCH + col + 1]   = y1;
            yt[(r0+8)*YPITCH + col]     = y2;
            yt[(r0+8)*YPITCH + col + 1] = y3;
        }
    }
    __syncthreads();

    if (mode == 1) {
        // residual add on fp32 x [b][c][l], coalesced over l; update yt in place
        for (int r = w; r < OT; r += 8) {
            float* rowp = xio + ((size_t)b*CC + o0 + r)*LL + l0;
#pragma unroll
            for (int i = 0; i < LT/32; i++) {
                int li = i*32 + lane;
                float xn = rowp[li] + yt[r*YPITCH + li];
                rowp[li] = xn;
                yt[r*YPITCH + li] = xn;
            }
        }
        __syncthreads();
    }

    // transposed bf16 hi/lo store: [b][l][c], coalesced over c
    const size_t lrow0 = ((size_t)b*XL + XPAD + l0)*CC + o0;
    for (int li = w; li < LT; li += 8) {
        float v0 = yt[lane*YPITCH + li];
        float v1 = yt[(lane+32)*YPITCH + li];
        __nv_bfloat16 h0 = __float2bfloat16_rn(v0);
        __nv_bfloat16 l0b = __float2bfloat16_rn(v0 - __bfloat162float(h0));
        __nv_bfloat16 h1 = __float2bfloat16_rn(v1);
        __nv_bfloat16 l1b = __float2bfloat16_rn(v1 - __bfloat162float(h1));
        size_t off = lrow0 + (size_t)li*CC + lane;
        out_hi[off] = h0;      out_hi[off + 32] = h1;
        out_lo[off] = l0b;     out_lo[off + 32] = l1b;
    }
}

// ---------------- host ----------------
extern "C" void kernel_launch(void* const* d_in, const int* in_sizes, int n_in,
                              void* d_out, int out_size) {
    const float* x = (const float*)d_in[0];
    float* out = (float*)d_out;

    void *qp, *xh, *xl, *hh, *hl;
    cudaGetSymbolAddress(&qp, g_q);
    cudaGetSymbolAddress(&xh, g_xt_hi);
    cudaGetSymbolAddress(&xl, g_xt_lo);
    cudaGetSymbolAddress(&hh, g_ht_hi);
    cudaGetSymbolAddress(&hl, g_ht_lo);
    __nv_bfloat16* qb  = (__nv_bfloat16*)qp;
    __nv_bfloat16* xhb = (__nv_bfloat16*)xh;
    __nv_bfloat16* xlb = (__nv_bfloat16*)xl;
    __nv_bfloat16* hhb = (__nv_bfloat16*)hh;
    __nv_bfloat16* hlb = (__nv_bfloat16*)hl;

    static int smem_set = 0;
    if (!smem_set) {
        cudaFuncSetAttribute(conv_mma_kernel, cudaFuncAttributeMaxDynamicSharedMemorySize, SMEM_TOTAL);
        smem_set = 1;
    }

    // Seed running x into d_out
    cudaMemcpyAsync(out, x, sizeof(float)*(size_t)BB*CC*LL, cudaMemcpyDeviceToDevice, 0);

    // Initial split+transpose of x
    transpose_split_k<<<dim3(LL/64, CC/32, BB), 256>>>(x);

    // Quantize all 6 weight tensors (w at d_in 1,3,5,7,9,11)
    for (int t = 0; t < 6; t++) {
        const float* wt = (const float*)d_in[1 + 2*t];
        absmean_partial_k<<<256, 256>>>(wt);
        absmean_final_k<<<1, 256>>>(t);
        quantize_k<<<(WELEMS + 255)/256, 256>>>(wt, t);
    }

    dim3 grid(CC/OT, LL/LT, BB);   // (8, 64, 8) — o fastest so same-X blocks are adjacent
    const int dils[3] = {1, 3, 5};
    for (int br = 0; br < 3; br++) {
        const float* bA = (const float*)d_in[2 + 4*br];
        const float* bB = (const float*)d_in[4 + 4*br];
        // h = leakyrelu(convA_dilated(x)) -> ht hi/lo
        conv_mma_kernel<<<grid, 256, SMEM_TOTAL>>>(
            qb + (size_t)(2*br)*3*CC*CC, xhb, xlb, bA, out, hhb, hlb, 2*br, dils[br], 0);
        // x += convB_dense(h); new x -> xt hi/lo
        conv_mma_kernel<<<grid, 256, SMEM_TOTAL>>>(
            qb + (size_t)(2*br+1)*3*CC*CC, hhb, hlb, bB, out, xhb, xlb, 2*br+1, 1, 1);
    }
}